// round 5
// baseline (speedup 1.0000x reference)
#include <cuda_runtime.h>
#include <math.h>

#define Bz 32
#define Sz 512
#define Dz 512
#define Hz 256
#define MR (Sz*Bz)
#define NC 2048
#define NB 64

__device__ float g_x0[MR * Dz];
__device__ float g_xpT[(size_t)NC * MR];
__device__ float g_h0[MR * 2 * Hz];
__device__ float g_h1[MR * 2 * Hz];
__device__ float g_hT[2 * 2 * Hz * Bz];
__device__ float g_nll[Bz];
__device__ unsigned g_cnt[2];
__device__ unsigned g_gen[2];

__device__ __forceinline__ unsigned ld_acq(const unsigned* p) {
    unsigned v;
    asm volatile("ld.acquire.gpu.global.u32 %0, [%1];" : "=r"(v) : "l"(p) : "memory");
    return v;
}
__device__ __forceinline__ void st_rel(unsigned* p, unsigned v) {
    asm volatile("st.release.gpu.global.u32 [%0], %1;" :: "l"(p), "r"(v) : "memory");
}

__global__ void embed_kernel(const int* __restrict__ ids, const int* __restrict__ msk,
                             const float* __restrict__ emb) {
    int row = blockIdx.x, t = row >> 5, b = row & 31;
    int id = ids[b * Sz + t];
    float mf = (float)msk[b * Sz + t];
    float4 v = ((const float4*)(emb + (size_t)id * Dz))[threadIdx.x];
    v.x *= mf; v.y *= mf; v.z *= mf; v.w *= mf;
    ((float4*)(g_x0 + (size_t)row * Dz))[threadIdx.x] = v;
}

/* xpT[col][row] = A[row][512] @ W[2048][512]^T + bias ; A chosen device-side */
__global__ void __launch_bounds__(256, 2)
sgemm_kernel(int layer, const float* __restrict__ W,
             const float* __restrict__ b1, const float* __restrict__ b2) {
    const float* A = layer ? g_h0 : g_x0;
    __shared__ float sA[8][128], sB[8][128];
    int tid = threadIdx.x;
    int m0 = blockIdx.y * 128, n0 = blockIdx.x * 128;
    int lr = tid >> 1, lk = (tid & 1) * 4;
    const float* Ap = A + (size_t)(m0 + lr) * Dz + lk;
    const float* Wp = W + (size_t)(n0 + lr) * Dz + lk;
    int ty = tid >> 4, tx = tid & 15;
    float acc[8][8];
#pragma unroll
    for (int i = 0; i < 8; i++)
#pragma unroll
        for (int j = 0; j < 8; j++) acc[i][j] = 0.0f;

    for (int k0 = 0; k0 < Dz; k0 += 8) {
        float4 va = *(const float4*)(Ap + k0);
        float4 vb = *(const float4*)(Wp + k0);
        sA[lk+0][lr] = va.x; sA[lk+1][lr] = va.y; sA[lk+2][lr] = va.z; sA[lk+3][lr] = va.w;
        sB[lk+0][lr] = vb.x; sB[lk+1][lr] = vb.y; sB[lk+2][lr] = vb.z; sB[lk+3][lr] = vb.w;
        __syncthreads();
#pragma unroll
        for (int kk = 0; kk < 8; kk++) {
            float4 a0 = *(const float4*)&sA[kk][ty*8], a1 = *(const float4*)&sA[kk][ty*8+4];
            float4 c0 = *(const float4*)&sB[kk][tx*8], c1 = *(const float4*)&sB[kk][tx*8+4];
            float av[8] = {a0.x,a0.y,a0.z,a0.w,a1.x,a1.y,a1.z,a1.w};
            float bv[8] = {c0.x,c0.y,c0.z,c0.w,c1.x,c1.y,c1.z,c1.w};
#pragma unroll
            for (int i = 0; i < 8; i++)
#pragma unroll
                for (int j = 0; j < 8; j++) acc[i][j] = fmaf(av[i], bv[j], acc[i][j]);
        }
        __syncthreads();
    }
#pragma unroll
    for (int j = 0; j < 8; j++) {
        int col = n0 + tx * 8 + j;
        float bs = b1[col] + b2[col];
        float* Cp = g_xpT + (size_t)col * MR + m0 + ty * 8;
#pragma unroll
        for (int i = 0; i < 8; i++) Cp[i] = acc[i][j] + bs;
    }
}

/* persistent BiLSTM: grid(64,2), 128 thr; CTA owns 4 units (16 gate rows) */
__global__ void __launch_bounds__(128, 1)
lstm_kernel(int layer, const float* __restrict__ whh) {
    float* hseq = layer ? g_h1 : g_h0;
    __shared__ float sWT[256 * 16];
    __shared__ float sH[256 * 32];
    int tid = threadIdx.x, d = blockIdx.y, cta = blockIdx.x;

    for (int idx = tid; idx < 4096; idx += 128) {
        int r = idx >> 8, k = idx & 255;
        sWT[k * 16 + r] = whh[(size_t)(d*1024 + (r>>2)*256 + cta*4 + (r&3))*256 + k];
    }
    int ks = tid >> 5, rg = (tid >> 3) & 3, bg = tid & 7;
    int ul = tid >> 5, b = tid & 31;
    float c = 0.0f;
    __syncthreads();

    for (int s = 0; s < Sz; s++) {
        int t = d ? (Sz - 1 - s) : s;
        if (s > 0) {
            const float* src = g_hT + (((s-1)&1)*2 + d) * Hz * Bz;
#pragma unroll 4
            for (int idx = tid; idx < Hz*Bz; idx += 128) sH[idx] = src[idx];
        }
        __syncthreads();

        float acc[4][4];
#pragma unroll
        for (int i = 0; i < 4; i++)
#pragma unroll
            for (int j = 0; j < 4; j++) acc[i][j] = 0.0f;
        if (s > 0) {
            int kb = ks * 64;
#pragma unroll 4
            for (int kk = 0; kk < 64; kk++) {
                int k = kb + kk;
                float4 w4 = *(const float4*)&sWT[k*16 + rg*4];
                float4 h4 = *(const float4*)&sH[k*32 + bg*4];
                float wa[4] = {w4.x,w4.y,w4.z,w4.w};
                float ha[4] = {h4.x,h4.y,h4.z,h4.w};
#pragma unroll
                for (int i = 0; i < 4; i++)
#pragma unroll
                    for (int j = 0; j < 4; j++) acc[i][j] = fmaf(wa[i], ha[j], acc[i][j]);
            }
        }
        __syncthreads();                 /* reuse sH as reduce buffer */
        float* red = sH;
#pragma unroll
        for (int i = 0; i < 4; i++)
#pragma unroll
            for (int j = 0; j < 4; j++) red[(i*4+j)*132 + tid] = acc[i][j];
        __syncthreads();

        float g4[4];
#pragma unroll
        for (int q = 0; q < 4; q++) {
            float v = g_xpT[(size_t)(d*1024 + q*256 + cta*4 + ul)*MR + t*32 + b];
            int base = (ul*4 + (b&3))*132 + q*8 + (b>>2);
#pragma unroll
            for (int kq = 0; kq < 4; kq++) v += red[base + kq*32];
            g4[q] = v;
        }
        float gi = 1.0f/(1.0f+expf(-g4[0]));
        float gf = 1.0f/(1.0f+expf(-g4[1]));
        float gg = tanhf(g4[2]);
        float go = 1.0f/(1.0f+expf(-g4[3]));
        c = gf*c + gi*gg;
        float h = go * tanhf(c);
        int ug = cta*4 + ul;
        hseq[(size_t)(t*Bz + b)*(2*Hz) + d*Hz + ug] = h;
        g_hT[((s&1)*2 + d)*Hz*Bz + ug*Bz + b] = h;

        if (s < Sz - 1) {
            __threadfence();
            __syncthreads();
            if (tid == 0) {
                unsigned g = ld_acq(&g_gen[d]);
                if (atomicAdd(&g_cnt[d], 1u) == NB - 1u) {
                    g_cnt[d] = 0u;
                    __threadfence();
                    st_rel(&g_gen[d], g + 1u);
                } else {
                    while (ld_acq(&g_gen[d]) == g) { }
                }
            }
            __syncthreads();
        }
    }
}

__global__ void __launch_bounds__(256, 2)
ln_cls_kernel(const float* __restrict__ gam, const float* __restrict__ bet,
              const float* __restrict__ cw, const float* __restrict__ cb,
              float* __restrict__ out) {
    __shared__ float sw[9 * 512];
    int tid = threadIdx.x;
    for (int i = tid; i < 9*512; i += 256) sw[i] = cw[i];
    __syncthreads();
    int warp = tid >> 5, lane = tid & 31;
    int row = blockIdx.x * 8 + warp;
    const float* xr = g_h1 + (size_t)row * 512;
    float x[16], sum = 0.0f;
#pragma unroll
    for (int i = 0; i < 16; i++) { x[i] = xr[lane + i*32]; sum += x[i]; }
#pragma unroll
    for (int o = 16; o; o >>= 1) sum += __shfl_xor_sync(~0u, sum, o);
    float mu = sum * (1.0f/512.0f), v = 0.0f;
#pragma unroll
    for (int i = 0; i < 16; i++) { float dd = x[i]-mu; v += dd*dd; }
#pragma unroll
    for (int o = 16; o; o >>= 1) v += __shfl_xor_sync(~0u, v, o);
    float rs = rsqrtf(v * (1.0f/512.0f) + 1e-5f);
    float n[16];
#pragma unroll
    for (int i = 0; i < 16; i++) {
        int f = lane + i*32;
        n[i] = (x[i]-mu)*rs*gam[f] + bet[f];
    }
    float a[9];
#pragma unroll
    for (int l = 0; l < 9; l++) a[l] = 0.0f;
#pragma unroll
    for (int l = 0; l < 9; l++)
#pragma unroll
        for (int i = 0; i < 16; i++) a[l] = fmaf(n[i], sw[l*512 + lane + i*32], a[l]);
#pragma unroll
    for (int l = 0; l < 9; l++)
#pragma unroll
        for (int o = 16; o; o >>= 1) a[l] += __shfl_xor_sync(~0u, a[l], o);
    if (lane == 0) {
        int t = row >> 5, bb = row & 31;
        float* op = out + 1 + ((size_t)bb*512 + t)*9;
#pragma unroll
        for (int l = 0; l < 9; l++) op[l] = a[l] + cb[l];
    }
}

__global__ void crf_kernel(const float* __restrict__ out, const int* __restrict__ labels,
                           const int* __restrict__ lens, const float* __restrict__ tr) {
    int b = blockIdx.x, j = threadIdx.x;
    const float* lg = out + 1 + (size_t)b * 512 * 9;
    int len = lens[b];
    bool act = j < 9;
    float ti[9];
#pragma unroll
    for (int i = 0; i < 9; i++) ti[i] = act ? tr[i*11 + j] : 0.0f;
    float alpha = act ? (tr[99 + j] + lg[j]) : -1e30f;

    for (int t = 1; t < 512; t++) {
        float e = act ? lg[t*9 + j] : 0.0f;
        float av[9];
#pragma unroll
        for (int i = 0; i < 9; i++) av[i] = __shfl_sync(~0u, alpha, i) + ti[i];
        float m = av[0];
#pragma unroll
        for (int i = 1; i < 9; i++) m = fmaxf(m, av[i]);
        float s2 = 0.0f;
#pragma unroll
        for (int i = 0; i < 9; i++) s2 += expf(av[i] - m);
        float nw = m + logf(s2) + e;
        if (act && t < len) alpha = nw;
    }
    float z = act ? (alpha + tr[j*11 + 10]) : -1e30f;
    float m = z;
#pragma unroll
    for (int o = 16; o; o >>= 1) m = fmaxf(m, __shfl_xor_sync(~0u, m, o));
    float es = expf(z - m);
#pragma unroll
    for (int o = 16; o; o >>= 1) es += __shfl_xor_sync(~0u, es, o);
    float logZ = m + logf(es);

    const int* lab = labels + b * 512;
    float sc = 0.0f;
    for (int t = j; t < 512; t += 32) {
        if (t < len) {
            int lt = lab[t];
            sc += lg[t*9 + lt];
            if (t >= 1) sc += tr[lab[t-1]*11 + lt];
        }
    }
#pragma unroll
    for (int o = 16; o; o >>= 1) sc += __shfl_xor_sync(~0u, sc, o);
    if (j == 0) {
        float gold = sc + tr[99 + lab[0]] + tr[lab[len-1]*11 + 10];
        g_nll[b] = logZ - gold;
    }
}

__global__ void reduce_kernel(float* __restrict__ out) {
    float v = g_nll[threadIdx.x];
#pragma unroll
    for (int o = 16; o; o >>= 1) v += __shfl_xor_sync(~0u, v, o);
    if (threadIdx.x == 0) out[0] = v * (1.0f/32.0f);
}

extern "C" void kernel_launch(void* const* d_in, const int* in_sizes, int n_in,
                              void* d_out, int out_size) {
    const int*   ids  = (const int*)d_in[0];
    const int*   msk  = (const int*)d_in[1];
    const int*   lens = (const int*)d_in[2];
    const int*   labs = (const int*)d_in[3];
    const float* emb  = (const float*)d_in[4];
    const float* wih  = (const float*)d_in[5];
    const float* whh  = (const float*)d_in[6];
    const float* bih  = (const float*)d_in[7];
    const float* bhh  = (const float*)d_in[8];
    const float* gam  = (const float*)d_in[9];
    const float* bet  = (const float*)d_in[10];
    const float* cw   = (const float*)d_in[11];
    const float* cb   = (const float*)d_in[12];
    const float* tr   = (const float*)d_in[13];
    float* out = (float*)d_out;

    embed_kernel<<<MR, 128>>>(ids, msk, emb);

    dim3 gg(16, 128);
    sgemm_kernel<<<gg, 256>>>(0, wih, bih, bhh);
    lstm_kernel<<<dim3(NB, 2), 128>>>(0, whh);

    sgemm_kernel<<<gg, 256>>>(1, wih + (size_t)2*1024*512, bih + 2048, bhh + 2048);
    lstm_kernel<<<dim3(NB, 2), 128>>>(1, whh + (size_t)2*1024*256);

    ln_cls_kernel<<<MR/8, 256>>>(gam, bet, cw, cb, out);
    crf_kernel<<<Bz, 32>>>(out, labs, lens, tr);
    reduce_kernel<<<1, 32>>>(out);
}

// round 6
// speedup vs baseline: 1.2299x; 1.2299x over previous
#include <cuda_runtime.h>
#include <math.h>

#define Bz 32
#define Sz 512
#define Dz 512
#define Hz 256
#define MR (Sz*Bz)
#define NC 2048
#define NB 64
typedef unsigned long long ull;

__device__ float g_x0[MR * Dz];
__device__ float g_xpT[(size_t)NC * MR];
__device__ float g_h0[MR * 2 * Hz];
__device__ float g_h1[MR * 2 * Hz];
__device__ float g_hT[2 * 2 * Hz * Bz];
__device__ float g_nll[Bz];
__device__ unsigned g_cnt[2];
__device__ unsigned g_gen[2];

__device__ __forceinline__ unsigned ld_acq(const unsigned* p) {
    unsigned v;
    asm volatile("ld.acquire.gpu.global.u32 %0, [%1];" : "=r"(v) : "l"(p) : "memory");
    return v;
}
__device__ __forceinline__ void st_rel(unsigned* p, unsigned v) {
    asm volatile("st.release.gpu.global.u32 [%0], %1;" :: "l"(p), "r"(v) : "memory");
}
__device__ __forceinline__ void ffma2(ull& d, ull a, ull b) {
    asm("fma.rn.f32x2 %0, %1, %2, %0;" : "+l"(d) : "l"(a), "l"(b));
}
__device__ __forceinline__ ull pk2(float lo, float hi) {
    ull r; asm("mov.b64 %0, {%1, %2};" : "=l"(r) : "f"(lo), "f"(hi)); return r;
}
__device__ __forceinline__ float2 upk2(ull v) {
    float2 r; asm("mov.b64 {%0, %1}, %2;" : "=f"(r.x), "=f"(r.y) : "l"(v)); return r;
}

__global__ void embed_kernel(const int* __restrict__ ids, const int* __restrict__ msk,
                             const float* __restrict__ emb) {
    int row = blockIdx.x, t = row >> 5, b = row & 31;
    int id = ids[b * Sz + t];
    float mf = (float)msk[b * Sz + t];
    float4 v = ((const float4*)(emb + (size_t)id * Dz))[threadIdx.x];
    v.x *= mf; v.y *= mf; v.z *= mf; v.w *= mf;
    ((float4*)(g_x0 + (size_t)row * Dz))[threadIdx.x] = v;
}

/* xpT[col][row] = A[row][512] @ W[2048][512]^T + bias, f32x2 inner product */
__global__ void __launch_bounds__(256, 2)
sgemm_kernel(int layer, const float* __restrict__ W,
             const float* __restrict__ b1, const float* __restrict__ b2) {
    const float* A = layer ? g_h0 : g_x0;
    __shared__ float sA2[8][256];   /* duplicated pairs {a,a} */
    __shared__ float sB[8][128];
    int tid = threadIdx.x;
    int m0 = blockIdx.y * 128, n0 = blockIdx.x * 128;
    int lr = tid >> 1, lk = (tid & 1) * 4;
    const float* Ap = A + (size_t)(m0 + lr) * Dz + lk;
    const float* Wp = W + (size_t)(n0 + lr) * Dz + lk;
    int ty = tid >> 4, tx = tid & 15;
    ull acc2[8][4];
#pragma unroll
    for (int i = 0; i < 8; i++)
#pragma unroll
        for (int p = 0; p < 4; p++) acc2[i][p] = 0ull;

    for (int k0 = 0; k0 < Dz; k0 += 8) {
        float4 va = *(const float4*)(Ap + k0);
        float4 vb = *(const float4*)(Wp + k0);
        *(float2*)&sA2[lk+0][2*lr] = make_float2(va.x, va.x);
        *(float2*)&sA2[lk+1][2*lr] = make_float2(va.y, va.y);
        *(float2*)&sA2[lk+2][2*lr] = make_float2(va.z, va.z);
        *(float2*)&sA2[lk+3][2*lr] = make_float2(va.w, va.w);
        sB[lk+0][lr] = vb.x; sB[lk+1][lr] = vb.y; sB[lk+2][lr] = vb.z; sB[lk+3][lr] = vb.w;
        __syncthreads();
#pragma unroll
        for (int kk = 0; kk < 8; kk++) {
            const float* ap = &sA2[kk][ty * 16];
            const float* bp = &sB[kk][tx * 8];
            ull a[8], b[4];
#pragma unroll
            for (int i = 0; i < 8; i++) a[i] = *(const ull*)(ap + 2 * i);
#pragma unroll
            for (int p = 0; p < 4; p++) b[p] = *(const ull*)(bp + 2 * p);
#pragma unroll
            for (int i = 0; i < 8; i++)
#pragma unroll
                for (int p = 0; p < 4; p++) ffma2(acc2[i][p], a[i], b[p]);
        }
        __syncthreads();
    }
    float acc[8][8];
#pragma unroll
    for (int i = 0; i < 8; i++)
#pragma unroll
        for (int p = 0; p < 4; p++) {
            float2 u = upk2(acc2[i][p]);
            acc[i][2*p] = u.x; acc[i][2*p+1] = u.y;
        }
#pragma unroll
    for (int j = 0; j < 8; j++) {
        int col = n0 + tx * 8 + j;
        float bs = b1[col] + b2[col];
        float* Cp = g_xpT + (size_t)col * MR + m0 + ty * 8;
#pragma unroll
        for (int i = 0; i < 8; i++) Cp[i] = acc[i][j] + bs;
    }
}

/* persistent BiLSTM: grid(64,2), 256 thr (ks8 x rg4 x bg8), tile 4x4, f32x2 */
__global__ void __launch_bounds__(256, 1)
lstm_kernel(int layer, const float* __restrict__ whh) {
    float* hseq = layer ? g_h1 : g_h0;
    __shared__ float sWT[256 * 16];     /* [k][r] 16KB */
    __shared__ float sH[256 * 32];      /* [k][b] 32KB, aliased as red[16][264] */
    int tid = threadIdx.x, d = blockIdx.y, cta = blockIdx.x;

    for (int idx = tid; idx < 4096; idx += 256) {
        int r = idx >> 8, k = idx & 255;
        sWT[k * 16 + r] = whh[(size_t)(d*1024 + (r>>2)*256 + cta*4 + (r&3))*256 + k];
    }
    int ks = tid >> 5, rg = (tid >> 3) & 3, bg = tid & 7;
    int ul = tid >> 5, b = tid & 31;    /* epilogue mapping (tid<128) */
    float c = 0.0f;
    __syncthreads();

    for (int s = 0; s < Sz; s++) {
        int t = d ? (Sz - 1 - s) : s;
        float xv[4];
        if (tid < 128) {                 /* hoisted gate-projection loads */
#pragma unroll
            for (int q = 0; q < 4; q++)
                xv[q] = g_xpT[(size_t)(d*1024 + q*256 + cta*4 + ul)*MR + t*32 + b];
        }
        if (s > 0) {
            const float* src = g_hT + (((s-1)&1)*2 + d) * Hz * Bz;
#pragma unroll 4
            for (int idx = tid; idx < Hz*Bz; idx += 256)
                sH[idx] = src[idx];
        }
        __syncthreads();

        ull acc2[4][2];
#pragma unroll
        for (int i = 0; i < 4; i++) { acc2[i][0] = 0ull; acc2[i][1] = 0ull; }
        if (s > 0) {
            int kb = ks * 32;
#pragma unroll 4
            for (int kk = 0; kk < 32; kk++) {
                int k = kb + kk;
                float4 w4 = *(const float4*)&sWT[k*16 + rg*4];
                float4 h4 = *(const float4*)&sH[k*32 + bg*4];
                ull hp0 = pk2(h4.x, h4.y), hp1 = pk2(h4.z, h4.w);
                ull wd[4] = {pk2(w4.x,w4.x), pk2(w4.y,w4.y), pk2(w4.z,w4.z), pk2(w4.w,w4.w)};
#pragma unroll
                for (int i = 0; i < 4; i++) {
                    ffma2(acc2[i][0], wd[i], hp0);
                    ffma2(acc2[i][1], wd[i], hp1);
                }
            }
        }
        __syncthreads();                 /* sH free -> reduce buffer */
        float* red = sH;
#pragma unroll
        for (int i = 0; i < 4; i++) {
            float2 u0 = upk2(acc2[i][0]), u1 = upk2(acc2[i][1]);
            red[(i*4+0)*264 + tid] = u0.x;
            red[(i*4+1)*264 + tid] = u0.y;
            red[(i*4+2)*264 + tid] = u1.x;
            red[(i*4+3)*264 + tid] = u1.y;
        }
        __syncthreads();

        if (tid < 128) {
            float g4[4];
#pragma unroll
            for (int q = 0; q < 4; q++) {
                float v = xv[q];
                int base = (ul*4 + (b&3))*264 + q*8 + (b>>2);
#pragma unroll
                for (int kq = 0; kq < 8; kq++) v += red[base + kq*32];
                g4[q] = v;
            }
            float gi = 1.0f/(1.0f+expf(-g4[0]));
            float gf = 1.0f/(1.0f+expf(-g4[1]));
            float gg = tanhf(g4[2]);
            float go = 1.0f/(1.0f+expf(-g4[3]));
            c = gf*c + gi*gg;
            float h = go * tanhf(c);
            int ug = cta*4 + ul;
            hseq[(size_t)(t*Bz + b)*(2*Hz) + d*Hz + ug] = h;
            g_hT[((s&1)*2 + d)*Hz*Bz + ug*Bz + b] = h;
        }

        if (s < Sz - 1) {
            __threadfence();
            __syncthreads();
            if (tid == 0) {
                unsigned g = ld_acq(&g_gen[d]);
                if (atomicAdd(&g_cnt[d], 1u) == NB - 1u) {
                    g_cnt[d] = 0u;
                    __threadfence();
                    st_rel(&g_gen[d], g + 1u);
                } else {
                    while (ld_acq(&g_gen[d]) == g) { }
                }
            }
            __syncthreads();
        }
    }
}

__global__ void __launch_bounds__(256, 2)
ln_cls_kernel(const float* __restrict__ gam, const float* __restrict__ bet,
              const float* __restrict__ cw, const float* __restrict__ cb,
              float* __restrict__ out) {
    __shared__ float sw[9 * 512];
    int tid = threadIdx.x;
    for (int i = tid; i < 9*512; i += 256) sw[i] = cw[i];
    __syncthreads();
    int warp = tid >> 5, lane = tid & 31;
    int row = blockIdx.x * 8 + warp;
    const float* xr = g_h1 + (size_t)row * 512;
    float x[16], sum = 0.0f;
#pragma unroll
    for (int i = 0; i < 16; i++) { x[i] = xr[lane + i*32]; sum += x[i]; }
#pragma unroll
    for (int o = 16; o; o >>= 1) sum += __shfl_xor_sync(~0u, sum, o);
    float mu = sum * (1.0f/512.0f), v = 0.0f;
#pragma unroll
    for (int i = 0; i < 16; i++) { float dd = x[i]-mu; v += dd*dd; }
#pragma unroll
    for (int o = 16; o; o >>= 1) v += __shfl_xor_sync(~0u, v, o);
    float rs = rsqrtf(v * (1.0f/512.0f) + 1e-5f);
    float n[16];
#pragma unroll
    for (int i = 0; i < 16; i++) {
        int f = lane + i*32;
        n[i] = (x[i]-mu)*rs*gam[f] + bet[f];
    }
    float a[9];
#pragma unroll
    for (int l = 0; l < 9; l++) a[l] = 0.0f;
#pragma unroll
    for (int l = 0; l < 9; l++)
#pragma unroll
        for (int i = 0; i < 16; i++) a[l] = fmaf(n[i], sw[l*512 + lane + i*32], a[l]);
#pragma unroll
    for (int l = 0; l < 9; l++)
#pragma unroll
        for (int o = 16; o; o >>= 1) a[l] += __shfl_xor_sync(~0u, a[l], o);
    if (lane == 0) {
        int t = row >> 5, bb = row & 31;
        float* op = out + 1 + ((size_t)bb*512 + t)*9;
#pragma unroll
        for (int l = 0; l < 9; l++) op[l] = a[l] + cb[l];
    }
}

__global__ void crf_kernel(const float* __restrict__ out, const int* __restrict__ labels,
                           const int* __restrict__ lens, const float* __restrict__ tr) {
    int b = blockIdx.x, j = threadIdx.x;
    const float* lg = out + 1 + (size_t)b * 512 * 9;
    int len = lens[b];
    bool act = j < 9;
    float ti[9];
#pragma unroll
    for (int i = 0; i < 9; i++) ti[i] = act ? tr[i*11 + j] : 0.0f;
    float alpha = act ? (tr[99 + j] + lg[j]) : -1e30f;

    for (int t = 1; t < 512; t++) {
        float e = act ? lg[t*9 + j] : 0.0f;
        float av[9];
#pragma unroll
        for (int i = 0; i < 9; i++) av[i] = __shfl_sync(~0u, alpha, i) + ti[i];
        float m = av[0];
#pragma unroll
        for (int i = 1; i < 9; i++) m = fmaxf(m, av[i]);
        float s2 = 0.0f;
#pragma unroll
        for (int i = 0; i < 9; i++) s2 += expf(av[i] - m);
        float nw = m + logf(s2) + e;
        if (act && t < len) alpha = nw;
    }
    float z = act ? (alpha + tr[j*11 + 10]) : -1e30f;
    float m = z;
#pragma unroll
    for (int o = 16; o; o >>= 1) m = fmaxf(m, __shfl_xor_sync(~0u, m, o));
    float es = expf(z - m);
#pragma unroll
    for (int o = 16; o; o >>= 1) es += __shfl_xor_sync(~0u, es, o);
    float logZ = m + logf(es);

    const int* lab = labels + b * 512;
    float sc = 0.0f;
    for (int t = j; t < 512; t += 32) {
        if (t < len) {
            int lt = lab[t];
            sc += lg[t*9 + lt];
            if (t >= 1) sc += tr[lab[t-1]*11 + lt];
        }
    }
#pragma unroll
    for (int o = 16; o; o >>= 1) sc += __shfl_xor_sync(~0u, sc, o);
    if (j == 0) {
        float gold = sc + tr[99 + lab[0]] + tr[lab[len-1]*11 + 10];
        g_nll[b] = logZ - gold;
    }
}

__global__ void reduce_kernel(float* __restrict__ out) {
    float v = g_nll[threadIdx.x];
#pragma unroll
    for (int o = 16; o; o >>= 1) v += __shfl_xor_sync(~0u, v, o);
    if (threadIdx.x == 0) out[0] = v * (1.0f/32.0f);
}

extern "C" void kernel_launch(void* const* d_in, const int* in_sizes, int n_in,
                              void* d_out, int out_size) {
    const int*   ids  = (const int*)d_in[0];
    const int*   msk  = (const int*)d_in[1];
    const int*   lens = (const int*)d_in[2];
    const int*   labs = (const int*)d_in[3];
    const float* emb  = (const float*)d_in[4];
    const float* wih  = (const float*)d_in[5];
    const float* whh  = (const float*)d_in[6];
    const float* bih  = (const float*)d_in[7];
    const float* bhh  = (const float*)d_in[8];
    const float* gam  = (const float*)d_in[9];
    const float* bet  = (const float*)d_in[10];
    const float* cw   = (const float*)d_in[11];
    const float* cb   = (const float*)d_in[12];
    const float* tr   = (const float*)d_in[13];
    float* out = (float*)d_out;

    embed_kernel<<<MR, 128>>>(ids, msk, emb);

    dim3 gg(16, 128);
    sgemm_kernel<<<gg, 256>>>(0, wih, bih, bhh);
    lstm_kernel<<<dim3(NB, 2), 256>>>(0, whh);

    sgemm_kernel<<<gg, 256>>>(1, wih + (size_t)2*1024*512, bih + 2048, bhh + 2048);
    lstm_kernel<<<dim3(NB, 2), 256>>>(1, whh + (size_t)2*1024*256);

    ln_cls_kernel<<<MR/8, 256>>>(gam, bet, cw, cb, out);
    crf_kernel<<<Bz, 32>>>(out, labs, lens, tr);
    reduce_kernel<<<1, 32>>>(out);
}

// round 8
// speedup vs baseline: 1.5373x; 1.2499x over previous
#include <cuda_runtime.h>
#include <math.h>

#define Bz 32
#define Sz 512
#define Dz 512
#define Hz 256
#define MR (Sz*Bz)
#define NC 2048
#define NB 64
typedef unsigned long long ull;

__device__ float g_x0[MR * Dz];
__device__ float g_xpT[(size_t)NC * MR];
__device__ float g_h0[MR * 2 * Hz];
__device__ float g_h1[MR * 2 * Hz];
__device__ float g_hT[2 * 2 * Hz * Bz];
__device__ float g_nll[Bz];
__device__ unsigned g_cnt[2];
__device__ unsigned g_gen[2];

__device__ __forceinline__ unsigned ld_acq(const unsigned* p) {
    unsigned v;
    asm volatile("ld.acquire.gpu.global.u32 %0, [%1];" : "=r"(v) : "l"(p) : "memory");
    return v;
}
__device__ __forceinline__ void st_rel(unsigned* p, unsigned v) {
    asm volatile("st.release.gpu.global.u32 [%0], %1;" :: "l"(p), "r"(v) : "memory");
}
__device__ __forceinline__ unsigned atom_add_rel(unsigned* p, unsigned v) {
    unsigned old;
    asm volatile("atom.release.gpu.global.add.u32 %0, [%1], %2;"
                 : "=r"(old) : "l"(p), "r"(v) : "memory");
    return old;
}
__device__ __forceinline__ void ffma2(ull& d, ull a, ull b) {
    asm("fma.rn.f32x2 %0, %1, %2, %0;" : "+l"(d) : "l"(a), "l"(b));
}
__device__ __forceinline__ ull pk2(float lo, float hi) {
    ull r; asm("mov.b64 %0, {%1, %2};" : "=l"(r) : "f"(lo), "f"(hi)); return r;
}
__device__ __forceinline__ float2 upk2(ull v) {
    float2 r; asm("mov.b64 {%0, %1}, %2;" : "=f"(r.x), "=f"(r.y) : "l"(v)); return r;
}
__device__ __forceinline__ float fsig(float x) { return 1.0f / (1.0f + __expf(-x)); }
__device__ __forceinline__ float ftanh(float x) { return 1.0f - 2.0f / (1.0f + __expf(2.0f * x)); }

__global__ void embed_kernel(const int* __restrict__ ids, const int* __restrict__ msk,
                             const float* __restrict__ emb) {
    int row = blockIdx.x, t = row >> 5, b = row & 31;
    int id = ids[b * Sz + t];
    float mf = (float)msk[b * Sz + t];
    float4 v = ((const float4*)(emb + (size_t)id * Dz))[threadIdx.x];
    v.x *= mf; v.y *= mf; v.z *= mf; v.w *= mf;
    ((float4*)(g_x0 + (size_t)row * Dz))[threadIdx.x] = v;
}

/* xpT[col][row] = A[row][512] @ W[2048][512]^T + bias, f32x2 inner product */
__global__ void __launch_bounds__(256, 2)
sgemm_kernel(int layer, const float* __restrict__ W,
             const float* __restrict__ b1, const float* __restrict__ b2) {
    const float* A = layer ? g_h0 : g_x0;
    __shared__ float sA2[8][256];
    __shared__ float sB[8][128];
    int tid = threadIdx.x;
    int m0 = blockIdx.y * 128, n0 = blockIdx.x * 128;
    int lr = tid >> 1, lk = (tid & 1) * 4;
    const float* Ap = A + (size_t)(m0 + lr) * Dz + lk;
    const float* Wp = W + (size_t)(n0 + lr) * Dz + lk;
    int ty = tid >> 4, tx = tid & 15;
    ull acc2[8][4];
#pragma unroll
    for (int i = 0; i < 8; i++)
#pragma unroll
        for (int p = 0; p < 4; p++) acc2[i][p] = 0ull;

    for (int k0 = 0; k0 < Dz; k0 += 8) {
        float4 va = *(const float4*)(Ap + k0);
        float4 vb = *(const float4*)(Wp + k0);
        *(float2*)&sA2[lk+0][2*lr] = make_float2(va.x, va.x);
        *(float2*)&sA2[lk+1][2*lr] = make_float2(va.y, va.y);
        *(float2*)&sA2[lk+2][2*lr] = make_float2(va.z, va.z);
        *(float2*)&sA2[lk+3][2*lr] = make_float2(va.w, va.w);
        sB[lk+0][lr] = vb.x; sB[lk+1][lr] = vb.y; sB[lk+2][lr] = vb.z; sB[lk+3][lr] = vb.w;
        __syncthreads();
#pragma unroll
        for (int kk = 0; kk < 8; kk++) {
            const float* ap = &sA2[kk][ty * 16];
            const float* bp = &sB[kk][tx * 8];
            ull a[8], b[4];
#pragma unroll
            for (int i = 0; i < 8; i++) a[i] = *(const ull*)(ap + 2 * i);
#pragma unroll
            for (int p = 0; p < 4; p++) b[p] = *(const ull*)(bp + 2 * p);
#pragma unroll
            for (int i = 0; i < 8; i++)
#pragma unroll
                for (int p = 0; p < 4; p++) ffma2(acc2[i][p], a[i], b[p]);
        }
        __syncthreads();
    }
#pragma unroll
    for (int j = 0; j < 8; j++) {
        int p = j >> 1, e = j & 1;
        int col = n0 + tx * 8 + j;
        float bs = b1[col] + b2[col];
        float* Cp = g_xpT + (size_t)col * MR + m0 + ty * 8;
#pragma unroll
        for (int i = 0; i < 8; i++) {
            float2 u = upk2(acc2[i][p]);
            Cp[i] = (e ? u.y : u.x) + bs;
        }
    }
}

/* persistent BiLSTM: grid(64,2), 512 thr (ks8 x rg4 x bs16), batch-paired f32x2 */
__global__ void __launch_bounds__(512, 1)
lstm_kernel(int layer, const float* __restrict__ whh) {
    float* hseq = layer ? g_h1 : g_h0;
    __shared__ float sWT[256 * 16];     /* [k][r], r = gate*4+unit   16KB */
    __shared__ float sH[256 * 32];      /* [k][b] 32KB; aliased red[r*32+b][9] */
    int tid = threadIdx.x, d = blockIdx.y, cta = blockIdx.x;

    for (int idx = tid; idx < 4096; idx += 512) {
        int r = idx >> 8, k = idx & 255;
        sWT[k * 16 + r] = whh[(size_t)(d*1024 + (r>>2)*256 + cta*4 + (r&3))*256 + k];
    }
    int ks = tid >> 6, rg = (tid >> 4) & 3, bs = tid & 15;
    int ul = tid >> 5, b = tid & 31;    /* epilogue mapping (tid<128) */
    float c = 0.0f;
    __syncthreads();

    for (int s = 0; s < Sz; s++) {
        int t = d ? (Sz - 1 - s) : s;
        float xv[4];
        if (tid < 128) {
#pragma unroll
            for (int q = 0; q < 4; q++)
                xv[q] = g_xpT[(size_t)(d*1024 + q*256 + cta*4 + ul)*MR + t*32 + b];
        }
        if (s > 0) {
            const float4* src = (const float4*)(g_hT + (((s-1)&1)*2 + d) * Hz * Bz);
            float4* dst = (float4*)sH;
#pragma unroll
            for (int i = 0; i < 4; i++) dst[tid + i * 512] = src[tid + i * 512];
        }
        __syncthreads();

        ull acc2[4];
#pragma unroll
        for (int i = 0; i < 4; i++) acc2[i] = 0ull;
        if (s > 0) {
            int kb = ks * 32;
#pragma unroll 4
            for (int kk = 0; kk < 32; kk++) {
                int k = kb + kk;
                float4 w4 = *(const float4*)&sWT[k*16 + rg*4];
                ull hp = *(const ull*)&sH[k*32 + bs*2];
                ffma2(acc2[0], pk2(w4.x, w4.x), hp);
                ffma2(acc2[1], pk2(w4.y, w4.y), hp);
                ffma2(acc2[2], pk2(w4.z, w4.z), hp);
                ffma2(acc2[3], pk2(w4.w, w4.w), hp);
            }
        }
        __syncthreads();                 /* sH free -> reduce buffer */
        float* red = sH;                 /* red[(r*32+bb)*9 + ks] */
#pragma unroll
        for (int u = 0; u < 4; u++) {
            float2 uv = upk2(acc2[u]);
            int r = rg * 4 + u;
            red[(r*32 + 2*bs    )*9 + ks] = uv.x;
            red[(r*32 + 2*bs + 1)*9 + ks] = uv.y;
        }
        __syncthreads();

        if (tid < 128) {
            float g4[4];
#pragma unroll
            for (int q = 0; q < 4; q++) {
                float v = xv[q];
                const float* rp = &red[((q*4 + ul)*32 + b)*9];
#pragma unroll
                for (int kq = 0; kq < 8; kq++) v += rp[kq];
                g4[q] = v;
            }
            float gi = fsig(g4[0]);
            float gf = fsig(g4[1]);
            float gg = ftanh(g4[2]);
            float go = fsig(g4[3]);
            c = gf*c + gi*gg;
            float h = go * ftanh(c);
            int ug = cta*4 + ul;
            hseq[(size_t)(t*Bz + b)*(2*Hz) + d*Hz + ug] = h;
            g_hT[((s&1)*2 + d)*Hz*Bz + ug*Bz + b] = h;
        }

        if (s < Sz - 1) {
            __syncthreads();             /* all h stores done CTA-wide */
            if (tid == 0) {
                unsigned g = ld_acq(&g_gen[d]);
                if (atom_add_rel(&g_cnt[d], 1u) == NB - 1u) {
                    g_cnt[d] = 0u;
                    st_rel(&g_gen[d], g + 1u);
                } else {
                    while (ld_acq(&g_gen[d]) == g) { }
                }
            }
            __syncthreads();
        }
    }
}

__global__ void __launch_bounds__(256, 2)
ln_cls_kernel(const float* __restrict__ gam, const float* __restrict__ bet,
              const float* __restrict__ cw, const float* __restrict__ cb,
              float* __restrict__ out) {
    __shared__ float sw[9 * 512];
    int tid = threadIdx.x;
    for (int i = tid; i < 9*512; i += 256) sw[i] = cw[i];
    __syncthreads();
    int warp = tid >> 5, lane = tid & 31;
    int row = blockIdx.x * 8 + warp;
    const float* xr = g_h1 + (size_t)row * 512;
    float x[16], sum = 0.0f;
#pragma unroll
    for (int i = 0; i < 16; i++) { x[i] = xr[lane + i*32]; sum += x[i]; }
#pragma unroll
    for (int o = 16; o; o >>= 1) sum += __shfl_xor_sync(~0u, sum, o);
    float mu = sum * (1.0f/512.0f), v = 0.0f;
#pragma unroll
    for (int i = 0; i < 16; i++) { float dd = x[i]-mu; v += dd*dd; }
#pragma unroll
    for (int o = 16; o; o >>= 1) v += __shfl_xor_sync(~0u, v, o);
    float rs = rsqrtf(v * (1.0f/512.0f) + 1e-5f);
    float n[16];
#pragma unroll
    for (int i = 0; i < 16; i++) {
        int f = lane + i*32;
        n[i] = (x[i]-mu)*rs*gam[f] + bet[f];
    }
    float a[9];
#pragma unroll
    for (int l = 0; l < 9; l++) a[l] = 0.0f;
#pragma unroll
    for (int l = 0; l < 9; l++)
#pragma unroll
        for (int i = 0; i < 16; i++) a[l] = fmaf(n[i], sw[l*512 + lane + i*32], a[l]);
#pragma unroll
    for (int l = 0; l < 9; l++)
#pragma unroll
        for (int o = 16; o; o >>= 1) a[l] += __shfl_xor_sync(~0u, a[l], o);
    if (lane == 0) {
        int t = row >> 5, bb = row & 31;
        float* op = out + 1 + ((size_t)bb*512 + t)*9;
#pragma unroll
        for (int l = 0; l < 9; l++) op[l] = a[l] + cb[l];
    }
}

__global__ void crf_kernel(const float* __restrict__ out, const int* __restrict__ labels,
                           const int* __restrict__ lens, const float* __restrict__ tr) {
    int b = blockIdx.x, j = threadIdx.x;
    const float* lg = out + 1 + (size_t)b * 512 * 9;
    int len = lens[b];
    bool act = j < 9;
    float ti[9];
#pragma unroll
    for (int i = 0; i < 9; i++) ti[i] = act ? tr[i*11 + j] : 0.0f;
    float alpha = act ? (tr[99 + j] + lg[j]) : -1e30f;

    for (int t = 1; t < 512; t++) {
        float e = act ? lg[t*9 + j] : 0.0f;
        float av[9];
#pragma unroll
        for (int i = 0; i < 9; i++) av[i] = __shfl_sync(~0u, alpha, i) + ti[i];
        float m = av[0];
#pragma unroll
        for (int i = 1; i < 9; i++) m = fmaxf(m, av[i]);
        float s2 = 0.0f;
#pragma unroll
        for (int i = 0; i < 9; i++) s2 += __expf(av[i] - m);
        float nw = m + __logf(s2) + e;
        if (act && t < len) alpha = nw;
    }
    float z = act ? (alpha + tr[j*11 + 10]) : -1e30f;
    float m = z;
#pragma unroll
    for (int o = 16; o; o >>= 1) m = fmaxf(m, __shfl_xor_sync(~0u, m, o));
    float es = __expf(z - m);
#pragma unroll
    for (int o = 16; o; o >>= 1) es += __shfl_xor_sync(~0u, es, o);
    float logZ = m + __logf(es);

    const int* lab = labels + b * 512;
    float sc = 0.0f;
    for (int t = j; t < 512; t += 32) {
        if (t < len) {
            int lt = lab[t];
            sc += lg[t*9 + lt];
            if (t >= 1) sc += tr[lab[t-1]*11 + lt];
        }
    }
#pragma unroll
    for (int o = 16; o; o >>= 1) sc += __shfl_xor_sync(~0u, sc, o);
    if (j == 0) {
        float gold = sc + tr[99 + lab[0]] + tr[lab[len-1]*11 + 10];
        g_nll[b] = logZ - gold;
    }
}

__global__ void reduce_kernel(float* __restrict__ out) {
    float v = g_nll[threadIdx.x];
#pragma unroll
    for (int o = 16; o; o >>= 1) v += __shfl_xor_sync(~0u, v, o);
    if (threadIdx.x == 0) out[0] = v * (1.0f/32.0f);
}

extern "C" void kernel_launch(void* const* d_in, const int* in_sizes, int n_in,
                              void* d_out, int out_size) {
    const int*   ids  = (const int*)d_in[0];
    const int*   msk  = (const int*)d_in[1];
    const int*   lens = (const int*)d_in[2];
    const int*   labs = (const int*)d_in[3];
    const float* emb  = (const float*)d_in[4];
    const float* wih  = (const float*)d_in[5];
    const float* whh  = (const float*)d_in[6];
    const float* bih  = (const float*)d_in[7];
    const float* bhh  = (const float*)d_in[8];
    const float* gam  = (const float*)d_in[9];
    const float* bet  = (const float*)d_in[10];
    const float* cw   = (const float*)d_in[11];
    const float* cb   = (const float*)d_in[12];
    const float* tr   = (const float*)d_in[13];
    float* out = (float*)d_out;

    embed_kernel<<<MR, 128>>>(ids, msk, emb);

    dim3 gg(16, 128);
    sgemm_kernel<<<gg, 256>>>(0, wih, bih, bhh);
    lstm_kernel<<<dim3(NB, 2), 512>>>(0, whh);

    sgemm_kernel<<<gg, 256>>>(1, wih + (size_t)2*1024*512, bih + 2048, bhh + 2048);
    lstm_kernel<<<dim3(NB, 2), 512>>>(1, whh + (size_t)2*1024*256);

    ln_cls_kernel<<<MR/8, 256>>>(gam, bet, cw, cb, out);
    crf_kernel<<<Bz, 32>>>(out, labs, lens, tr);
    reduce_kernel<<<1, 32>>>(out);
}